// round 3
// baseline (speedup 1.0000x reference)
#include <cuda_runtime.h>
#include <cuda_bf16.h>

// Problem constants
#define NB 16
#define NC 256
#define HW 4096
#define ENH_ELEMS (NB * NC * HW)       // 16777216
#define ENT_ELEMS (NB * HW)            // 65536 per map

// ---------------- scratch (device globals; no allocation) ----------------
__device__ float g_pooled[2][NB][NC];
__device__ float g_cw[2][NB][NC];
__device__ float g_se[2][NB][HW];
__device__ float g_psum[2][NB][16];
__device__ float g_psq[2][NB][16];
__device__ float g_thr[2][NB];
__device__ float g_inv[2][NB];

// ---------------- entropy: log(p+eps) - (1-p)*log(1-p+eps), p=sigmoid(x) ---
// softplus form: log p = -softplus(-x), log(1-p) = -softplus(x)
// softplus(x) = max(x,0) + log(1+exp(-|x|)).  3 MUFU: EX2, LG2, RCP.
__device__ __forceinline__ float entropy_val(float x) {
    float a = fabsf(x);
    float t = __expf(-a);                  // e^{-|x|} in (0,1]
    float l = __logf(1.0f + t);            // log(1+e^{-|x|})
    float inv = __fdividef(1.0f, 1.0f + t);
    bool pos = (x >= 0.0f);
    float p      = pos ? inv        : t * inv;   // sigmoid(x)
    float logp   = pos ? -l         : (x - l);   // log p
    float log1mp = pos ? (-x - l)   : -l;        // log (1-p)
    return logp - (1.0f - p) * log1mp;
}

// ---------------- K1: pooled[b,c] = mean over HW ----------------
__global__ void k_pool(const float* __restrict__ vis, const float* __restrict__ text) {
    int id = blockIdx.x;              // 0..8191
    int f  = id >> 12;                // /4096 (= NB*NC)
    int bc = id & 4095;
    const float* feat = f ? text : vis;
    const float4* src = (const float4*)(feat + (size_t)bc * HW);
    float acc = 0.0f;
    #pragma unroll 4
    for (int i = threadIdx.x; i < HW / 4; i += 128) {
        float4 v = src[i];
        acc += (v.x + v.y) + (v.z + v.w);
    }
    #pragma unroll
    for (int o = 16; o; o >>= 1) acc += __shfl_xor_sync(0xffffffffu, acc, o);
    __shared__ float s[4];
    if ((threadIdx.x & 31) == 0) s[threadIdx.x >> 5] = acc;
    __syncthreads();
    if (threadIdx.x == 0) {
        float tsum = (s[0] + s[1]) + (s[2] + s[3]);
        int b = bc >> 8, c = bc & 255;
        g_pooled[f][b][c] = tsum * (1.0f / HW);
    }
}

// ---------------- K2: cw = sigmoid(relu(pooled@w1+b1)@w2+b2) ----------------
__global__ void k_mlp(const float* __restrict__ w1, const float* __restrict__ b1,
                      const float* __restrict__ w2, const float* __restrict__ b2) {
    int f = blockIdx.x >> 4, b = blockIdx.x & 15;
    __shared__ float sp[NC];
    __shared__ float sh[64];
    sp[threadIdx.x] = g_pooled[f][b][threadIdx.x];
    __syncthreads();
    if (threadIdx.x < 64) {
        float acc = b1[threadIdx.x];
        #pragma unroll 4
        for (int i = 0; i < NC; i++) acc = fmaf(sp[i], w1[i * 64 + threadIdx.x], acc);
        sh[threadIdx.x] = fmaxf(acc, 0.0f);
    }
    __syncthreads();
    float acc = b2[threadIdx.x];
    #pragma unroll 4
    for (int j = 0; j < 64; j++) acc = fmaf(sh[j], w2[j * NC + threadIdx.x], acc);
    g_cw[f][b][threadIdx.x] = __fdividef(1.0f, 1.0f + __expf(-acc));
}

// ---------------- K3: se[b,hw] = sum_c ent(feat)*cw  + block partials -------
__global__ void k_se(const float* __restrict__ vis, const float* __restrict__ text) {
    int bid   = blockIdx.x;           // 512 blocks
    int f     = bid >> 8;
    int b     = (bid >> 4) & 15;
    int chunk = bid & 15;             // 16 chunks of 256 pixels
    int pix   = chunk * 256 + threadIdx.x;
    const float* feat = (f ? text : vis) + (size_t)b * NC * HW + pix;

    __shared__ float scw[NC];
    scw[threadIdx.x] = g_cw[f][b][threadIdx.x];
    __syncthreads();

    float acc = 0.0f;
    #pragma unroll 8
    for (int c = 0; c < NC; c++) {
        float x = feat[(size_t)c * HW];
        acc = fmaf(entropy_val(x), scw[c], acc);
    }
    g_se[f][b][pix] = acc;

    float s = acc, q = acc * acc;
    #pragma unroll
    for (int o = 16; o; o >>= 1) {
        s += __shfl_xor_sync(0xffffffffu, s, o);
        q += __shfl_xor_sync(0xffffffffu, q, o);
    }
    __shared__ float ss[8], sq[8];
    if ((threadIdx.x & 31) == 0) { ss[threadIdx.x >> 5] = s; sq[threadIdx.x >> 5] = q; }
    __syncthreads();
    if (threadIdx.x == 0) {
        float S = 0.0f, Q = 0.0f;
        #pragma unroll
        for (int i = 0; i < 8; i++) { S += ss[i]; Q += sq[i]; }
        g_psum[f][b][chunk] = S;
        g_psq [f][b][chunk] = Q;
    }
}

// ---------------- K4: per-(f,b) threshold + inverse L2 norm ----------------
__global__ void k_stats() {
    int t = threadIdx.x;
    if (t >= 32) return;
    int f = t >> 4, b = t & 15;
    float S = 0.0f, Q = 0.0f;
    #pragma unroll
    for (int i = 0; i < 16; i++) { S += g_psum[f][b][i]; Q += g_psq[f][b][i]; }
    g_thr[f][b] = S * (0.5f / HW);                  // mean(se)*THRESHOLD (scale-free vs normalize)
    float norm = sqrtf(Q);
    g_inv[f][b] = 1.0f / fmaxf(norm, 1e-12f);
}

// ---------------- K5: enhanced = vis*mv + text*mt*(1-mv) (float4) ----------
__global__ void k_out(const float* __restrict__ vis, const float* __restrict__ text,
                      float* __restrict__ out) {
    int idx4 = blockIdx.x * 256 + threadIdx.x;      // 0 .. 4194303
    int pix4 = idx4 & 1023;                         // HW/4 = 1024
    int b    = idx4 >> 18;                          // / (NC*1024)
    float thr_v = g_thr[0][b];
    float thr_t = g_thr[1][b];
    float4 sev = ((const float4*)g_se[0][b])[pix4];
    float4 set = ((const float4*)g_se[1][b])[pix4];
    float4 v = ((const float4*)vis)[idx4];
    float4 t = ((const float4*)text)[idx4];
    float4 o;
    o.x = (sev.x < thr_v) ? v.x : ((set.x < thr_t) ? t.x : 0.0f);
    o.y = (sev.y < thr_v) ? v.y : ((set.y < thr_t) ? t.y : 0.0f);
    o.z = (sev.z < thr_v) ? v.z : ((set.z < thr_t) ? t.z : 0.0f);
    o.w = (sev.w < thr_v) ? v.w : ((set.w < thr_t) ? t.w : 0.0f);
    ((float4*)out)[idx4] = o;
}

// ---------------- K6: normalized entropy maps into output tail -------------
__global__ void k_ent(float* __restrict__ out) {
    int idx = blockIdx.x * 256 + threadIdx.x;       // 0 .. 131071
    int f   = idx >> 16;
    int rem = idx & 65535;
    int b   = rem >> 12;
    int pix = rem & 4095;
    out[ENH_ELEMS + idx] = g_se[f][b][pix] * g_inv[f][b];
}

// ---------------- launch ----------------
extern "C" void kernel_launch(void* const* d_in, const int* in_sizes, int n_in,
                              void* d_out, int out_size) {
    const float* vis  = (const float*)d_in[0];
    const float* text = (const float*)d_in[1];
    const float* w1   = (const float*)d_in[2];
    const float* b1   = (const float*)d_in[3];
    const float* w2   = (const float*)d_in[4];
    const float* b2   = (const float*)d_in[5];
    float* out = (float*)d_out;

    k_pool <<<2 * NB * NC, 128>>>(vis, text);
    k_mlp  <<<2 * NB, NC>>>(w1, b1, w2, b2);
    k_se   <<<2 * NB * 16, 256>>>(vis, text);
    k_stats<<<1, 32>>>();
    k_out  <<<ENH_ELEMS / 4 / 256, 256>>>(vis, text, out);
    k_ent  <<<2 * ENT_ELEMS / 256, 256>>>(out);
}